// round 9
// baseline (speedup 1.0000x reference)
#include <cuda_runtime.h>
#include <cuda_fp16.h>
#include <cstdint>

#define OFF_Q    0ull
#define OFF_LOSS 2097152ull
#define OFF_PERP 2097153ull
#define OFF_ENC  2097154ull
#define OFF_DIST 35651586ull

#define BSTRIDE 136     // u32 stride: conflict-free b-frag LDS
#define EPS_WIN 0.1f    // >= 2x max |approx-exact| dist error (5-sigma ~0.026)

__device__ int      g_counts[1024];
__device__ float    g_loss_sum;
__device__ float    g_wnorm[1024];
// codebook fp16 (hi part), layout [chunk(8)][kp(32)][code(128)] u32
__device__ __align__(16) uint32_t g_whi[32768];

static __device__ __forceinline__ uint32_t pack2h(float x, float y) {
    __half2 h = __floats2half2_rn(x, y);
    return *(uint32_t*)&h;
}

static __device__ __forceinline__ void mma16816(float* c, const uint32_t* a,
                                                uint32_t b0, uint32_t b1) {
    asm volatile(
        "mma.sync.aligned.m16n8k16.row.col.f32.f16.f16.f32 "
        "{%0,%1,%2,%3}, {%4,%5,%6,%7}, {%8,%9}, {%0,%1,%2,%3};"
        : "+f"(c[0]), "+f"(c[1]), "+f"(c[2]), "+f"(c[3])
        : "r"(a[0]), "r"(a[1]), "r"(a[2]), "r"(a[3]), "r"(b0), "r"(b1));
}

// --- k_pre: pack codebook hi-fp16 + wnorms + reset scratch ------------------
__global__ void k_pre(const float* __restrict__ W) {
    const int t    = blockIdx.x * 256 + threadIdx.x;   // 32768 threads
    const int code = t >> 5;
    const int kp   = t & 31;
    float2 v = ((const float2*)(W + (size_t)code * 64))[kp];
    const int chunk = code >> 7, c = code & 127;
    g_whi[(chunk * 32 + kp) * 128 + c] = pack2h(v.x, v.y);
    float s = v.x * v.x + v.y * v.y;
    #pragma unroll
    for (int off = 16; off > 0; off >>= 1)
        s += __shfl_xor_sync(~0u, s, off);
    if (kp == 0) g_wnorm[code] = s;
    if (t < 1024) g_counts[t] = 0;       // replay-deterministic reset
    if (t == 0)   g_loss_sum  = 0.f;
}

// --- k_gemm: approx distances (1-term fp16 mma) + dist/enc-zero stores ------
__global__ __launch_bounds__(256, 2)
void k_gemm(const float* __restrict__ latent, float* __restrict__ out) {
    __shared__ __align__(16) uint32_t SBHI[32 * BSTRIDE];
    __shared__ __align__(16) float s_wn[1024];

    const int tid  = threadIdx.x;
    const int blk  = blockIdx.x;
    const int w    = tid >> 5;
    const int lane = tid & 31;
    const int g    = lane >> 2;
    const int tg   = lane & 3;
    const int b    = blk >> 3;
    const int jb   = (blk & 7) * 128;

    const int row0 = w * 16 + g;
    const int row1 = row0 + 8;
    const size_t R0 = (size_t)(blk * 128 + row0);
    const size_t R1 = R0 + 8;

    ((float4*)s_wn)[tid] = ((const float4*)g_wnorm)[tid];

    // ---- A fragments (hi only) + full-precision row norms ----
    uint32_t ah[4][4];
    float xn0 = 0.f, xn1 = 0.f;
    {
        const float* LB = latent + (size_t)b * 65536 + jb;
        #pragma unroll
        for (int k = 0; k < 4; k++) {
            const int n0 = 16 * k + 2 * tg;
            float x00 = __ldcs(&LB[(size_t)(n0    ) * 1024 + row0]);
            float x01 = __ldcs(&LB[(size_t)(n0 + 1) * 1024 + row0]);
            float x10 = __ldcs(&LB[(size_t)(n0    ) * 1024 + row1]);
            float x11 = __ldcs(&LB[(size_t)(n0 + 1) * 1024 + row1]);
            float x20 = __ldcs(&LB[(size_t)(n0 + 8) * 1024 + row0]);
            float x21 = __ldcs(&LB[(size_t)(n0 + 9) * 1024 + row0]);
            float x30 = __ldcs(&LB[(size_t)(n0 + 8) * 1024 + row1]);
            float x31 = __ldcs(&LB[(size_t)(n0 + 9) * 1024 + row1]);
            ah[k][0] = pack2h(x00, x01);
            ah[k][1] = pack2h(x10, x11);
            ah[k][2] = pack2h(x20, x21);
            ah[k][3] = pack2h(x30, x31);
            xn0 += x00*x00 + x01*x01 + x20*x20 + x21*x21;
            xn1 += x10*x10 + x11*x11 + x30*x30 + x31*x31;
        }
        xn0 += __shfl_xor_sync(~0u, xn0, 1);
        xn0 += __shfl_xor_sync(~0u, xn0, 2);
        xn1 += __shfl_xor_sync(~0u, xn1, 1);
        xn1 += __shfl_xor_sync(~0u, xn1, 2);
    }

    const float2 zero2 = make_float2(0.f, 0.f);

    for (int ch = 0; ch < 8; ch++) {
        __syncthreads();
        // stage prepacked B-hi chunk (coalesced LDG.128 -> STS.128)
        {
            const uint4* GH = (const uint4*)(g_whi + ch * 4096);
            #pragma unroll
            for (int q = 0; q < 4; q++) {
                const int idx = tid + q * 256;
                const int kp = idx >> 5, c4 = idx & 31;
                *(uint4*)&SBHI[kp * BSTRIDE + c4 * 4] = GH[idx];
            }
        }
        __syncthreads();

        // coalesced streaming zero-fill of this chunk's enc slice
        {
            float2* eb = (float2*)(out + OFF_ENC) + (size_t)blk * 65536 + ch * 64;
            #pragma unroll
            for (int i = 0; i < 32; i++) {
                const int idx = i * 256 + tid;
                const int r = idx >> 6, c2 = idx & 63;
                __stcs(eb + (size_t)r * 512 + c2, zero2);
            }
        }

        // 16 n-tiles in 4 groups of 4 (1 mma term each)
        #pragma unroll
        for (int grp = 0; grp < 4; grp++) {
            float acc[4][4];
            #pragma unroll
            for (int t4 = 0; t4 < 4; t4++) {
                acc[t4][0] = 0.f; acc[t4][1] = 0.f;
                acc[t4][2] = 0.f; acc[t4][3] = 0.f;
            }
            #pragma unroll
            for (int k = 0; k < 4; k++) {
                #pragma unroll
                for (int t4 = 0; t4 < 4; t4++) {
                    const int nb = (grp * 4 + t4) * 8 + g;
                    const int kp = k * 8 + tg;
                    uint32_t bh0 = SBHI[(kp    ) * BSTRIDE + nb];
                    uint32_t bh1 = SBHI[(kp + 4) * BSTRIDE + nb];
                    mma16816(acc[t4], ah[k], bh0, bh1);
                }
            }
            #pragma unroll
            for (int t4 = 0; t4 < 4; t4++) {
                const int col = ch * 128 + (grp * 4 + t4) * 8 + 2 * tg;
                const float2 wn = *(const float2*)&s_wn[col];
                float d00 = fmaf(-2.f, acc[t4][0], xn0 + wn.x);
                float d01 = fmaf(-2.f, acc[t4][1], xn0 + wn.y);
                float d10 = fmaf(-2.f, acc[t4][2], xn1 + wn.x);
                float d11 = fmaf(-2.f, acc[t4][3], xn1 + wn.y);
                __stcs((float2*)(out + OFF_DIST + R0 * 1024 + col),
                       make_float2(d00, d01));
                __stcs((float2*)(out + OFF_DIST + R1 * 1024 + col),
                       make_float2(d10, d11));
            }
        }
    }
}

// --- k_argmin: exact argmin via candidate window + one-hot + quant + loss ---
// warp per row; block = 8 consecutive rows.
__global__ __launch_bounds__(256)
void k_argmin(const float* __restrict__ latent, const float* __restrict__ W,
              float* __restrict__ out) {
    __shared__ int   s_cnt[8];
    __shared__ int   s_cand[8][16];
    __shared__ float s_wq[64][8];
    __shared__ float s_lred[8];

    const int tid  = threadIdx.x;
    const int w    = tid >> 5;
    const int lane = tid & 31;
    const int t    = blockIdx.x * 8 + w;

    // read this row's stored approx distances (float2: OFF_DIST is 8B-aligned)
    const float2* drow = (const float2*)(out + OFF_DIST + (size_t)t * 1024);
    float2 dv[16];
    #pragma unroll
    for (int i = 0; i < 16; i++) dv[i] = __ldcs(&drow[i * 32 + lane]);

    float m = 3.4e38f;
    #pragma unroll
    for (int i = 0; i < 16; i++) m = fminf(m, fminf(dv[i].x, dv[i].y));
    #pragma unroll
    for (int off = 16; off > 0; off >>= 1)
        m = fminf(m, __shfl_xor_sync(~0u, m, off));

    if (lane == 0) s_cnt[w] = 0;
    __syncwarp();

    const float thr = m + EPS_WIN;
    #pragma unroll
    for (int i = 0; i < 16; i++) {
        const int c0 = (i * 32 + lane) * 2;
        if (dv[i].x < thr) {
            int p = atomicAdd(&s_cnt[w], 1);
            if (p < 16) s_cand[w][p] = c0;
        }
        if (dv[i].y < thr) {
            int p = atomicAdd(&s_cnt[w], 1);
            if (p < 16) s_cand[w][p] = c0 + 1;
        }
    }
    __syncwarp();

    int cnt = s_cnt[w];
    if (cnt > 16) cnt = 16;
    int bi = s_cand[w][0];

    if (cnt > 1) {
        // exact fp32 refinement over the (rare) candidate set
        const int bb = t >> 10, pos = t & 1023;
        float2 x2;
        x2.x = latent[(size_t)bb * 65536 + (size_t)(2 * lane    ) * 1024 + pos];
        x2.y = latent[(size_t)bb * 65536 + (size_t)(2 * lane + 1) * 1024 + pos];
        float xn = x2.x * x2.x + x2.y * x2.y;
        #pragma unroll
        for (int off = 16; off > 0; off >>= 1)
            xn += __shfl_xor_sync(~0u, xn, off);
        float bd = 3.4e38f;
        bi = 1 << 30;
        for (int s = 0; s < cnt; s++) {
            const int c = s_cand[w][s];
            float2 w2 = ((const float2*)(W + (size_t)c * 64))[lane];
            float p = fmaf(x2.x, w2.x, x2.y * w2.y);
            #pragma unroll
            for (int off = 16; off > 0; off >>= 1)
                p += __shfl_xor_sync(~0u, p, off);
            float d = fmaf(-2.f, p, xn + g_wnorm[c]);
            if (d < bd || (d == bd && c < bi)) { bd = d; bi = c; }
        }
    }

    if (lane == 0) {
        atomicAdd(&g_counts[bi], 1);
        out[OFF_ENC + (size_t)t * 1024 + bi] = 1.f;   // after k_gemm's zeros
        s_lred[w] = m;                                 // loss from approx min
    }

    // quantized gather: stage W[bi] per row, then coalesced transposed writes
    {
        float2 wv = ((const float2*)(W + (size_t)bi * 64))[lane];
        s_wq[2 * lane][w]     = wv.x;
        s_wq[2 * lane + 1][w] = wv.y;
    }
    __syncthreads();
    if (tid == 0) {
        float s = 0.f;
        #pragma unroll
        for (int i = 0; i < 8; i++) s += s_lred[i];
        atomicAdd(&g_loss_sum, s);
    }
    {
        const int t0 = blockIdx.x * 8;
        const int bb = t0 >> 10, pos0 = t0 & 1023;
        #pragma unroll
        for (int i = 0; i < 2; i++) {
            const int id = tid + i * 256;
            const int n = id >> 3, r = id & 7;
            __stcs(&out[OFF_Q + (size_t)bb * 65536 + (size_t)n * 1024 + pos0 + r],
                   s_wq[n][r]);
        }
    }
}

// --- k_final: perplexity + loss ----------------------------------------------
__global__ void k_final(float* __restrict__ out) {
    __shared__ float red[1024];
    const int k = threadIdx.x;
    const float p = (float)g_counts[k] / 32768.0f;
    red[k] = -p * logf(p + 1e-10f);
    __syncthreads();
    for (int s = 512; s > 0; s >>= 1) {
        if (k < s) red[k] += red[k + s];
        __syncthreads();
    }
    if (k == 0) {
        out[OFF_PERP] = expf(red[0]);
        out[OFF_LOSS] = 0.25f * g_loss_sum / 2097152.0f;
    }
}

// -----------------------------------------------------------------------------
extern "C" void kernel_launch(void* const* d_in, const int* in_sizes, int n_in,
                              void* d_out, int out_size) {
    const float* latent = (const float*)d_in[0];
    const float* W      = (const float*)d_in[1];
    float* out = (float*)d_out;

    k_pre   <<<128, 256>>>(W);
    k_gemm  <<<256, 256>>>(latent, out);
    k_argmin<<<4096, 256>>>(latent, W, out);
    k_final <<<1, 1024>>>(out);
}

// round 10
// speedup vs baseline: 1.4860x; 1.4860x over previous
#include <cuda_runtime.h>
#include <cuda_fp16.h>
#include <cstdint>

#define OFF_Q    0ull
#define OFF_LOSS 2097152ull
#define OFF_PERP 2097153ull
#define OFF_ENC  2097154ull
#define OFF_DIST 35651586ull

#define BSTRIDE 136   // u32 stride: conflict-free b-frag LDS

// dynamic smem partition (bytes)
#define SMO_B    0            // uint32[2*32*136] = 34816 B (B hi | B lo; wq reuse)
#define SMO_D    34816        // float[128*68]    = 34816 B (dist staging)
#define SMO_WN   69632        // float[1024]
#define SMO_RMIN 73728        // float[128]
#define SMO_RIDX 74240        // int[128]
#define SMO_LOSS 74752        // float[8]
#define SMEM_BYTES 74816

__device__ int      g_counts[1024];
__device__ float    g_loss_sum;
__device__ float    g_wnorm[1024];
// codebook packed fp16 hi/lo, layout [chunk(8)][kp(32)][code(128)] u32
__device__ __align__(16) uint32_t g_whi[32768];
__device__ __align__(16) uint32_t g_wlo[32768];

static __device__ __forceinline__ void split2(float x, float y,
                                              uint32_t& hi, uint32_t& lo) {
    __half hx = __float2half_rn(x), hy = __float2half_rn(y);
    float rx = x - __half2float(hx), ry = y - __half2float(hy);
    __half2 h = __halves2half2(hx, hy);
    __half2 l = __floats2half2_rn(rx, ry);
    hi = *(uint32_t*)&h;
    lo = *(uint32_t*)&l;
}

static __device__ __forceinline__ void mma16816(float* c, const uint32_t* a,
                                                uint32_t b0, uint32_t b1) {
    asm volatile(
        "mma.sync.aligned.m16n8k16.row.col.f32.f16.f16.f32 "
        "{%0,%1,%2,%3}, {%4,%5,%6,%7}, {%8,%9}, {%0,%1,%2,%3};"
        : "+f"(c[0]), "+f"(c[1]), "+f"(c[2]), "+f"(c[3])
        : "r"(a[0]), "r"(a[1]), "r"(a[2]), "r"(a[3]), "r"(b0), "r"(b1));
}

// --- k_pre: pack codebook fp16 hi/lo + wnorms + scratch reset ----------------
__global__ void k_pre(const float* __restrict__ W) {
    const int t    = blockIdx.x * 256 + threadIdx.x;   // 32768 threads
    const int code = t >> 5;
    const int kp   = t & 31;
    float2 v = ((const float2*)(W + (size_t)code * 64))[kp];
    uint32_t h, l;
    split2(v.x, v.y, h, l);
    const int chunk = code >> 7, c = code & 127;
    g_whi[(chunk * 32 + kp) * 128 + c] = h;
    g_wlo[(chunk * 32 + kp) * 128 + c] = l;
    float s = v.x * v.x + v.y * v.y;
    #pragma unroll
    for (int off = 16; off > 0; off >>= 1)
        s += __shfl_xor_sync(~0u, s, off);
    if (kp == 0) g_wnorm[code] = s;
    if (t < 1024) g_counts[t] = 0;       // replay-deterministic reset
    if (t == 0)   g_loss_sum  = 0.f;
}

// --- k_main: fused distances(mma) + argmin + enc + quantized + loss ---------
__global__ __launch_bounds__(256, 2)
void k_main(const float* __restrict__ latent, const float* __restrict__ W,
            float* __restrict__ out) {
    extern __shared__ __align__(16) char sm[];
    uint32_t* SBHI   = (uint32_t*)(sm + SMO_B);
    uint32_t* SBLO   = SBHI + 32 * BSTRIDE;
    float*    s_d    = (float*)(sm + SMO_D);
    float*    s_wn   = (float*)(sm + SMO_WN);
    float*    s_rmin = (float*)(sm + SMO_RMIN);
    int*      s_ridx = (int*)  (sm + SMO_RIDX);
    float*    s_loss = (float*)(sm + SMO_LOSS);

    const int tid  = threadIdx.x;
    const int blk  = blockIdx.x;
    const int w    = tid >> 5;
    const int lane = tid & 31;
    const int g    = lane >> 2;
    const int tg   = lane & 3;
    const int b    = blk >> 3;
    const int jb   = (blk & 7) * 128;

    const int row0 = w * 16 + g;
    const int row1 = row0 + 8;

    ((float4*)s_wn)[tid] = ((const float4*)g_wnorm)[tid];

    // ---- A fragments (hi/lo, resident) + fp32 row norms ----
    uint32_t ah[4][4], al[4][4];
    float xn0 = 0.f, xn1 = 0.f;
    {
        const float* LB = latent + (size_t)b * 65536 + jb;
        #pragma unroll
        for (int k = 0; k < 4; k++) {
            const int n0 = 16 * k + 2 * tg;
            float x00 = __ldcs(&LB[(size_t)(n0    ) * 1024 + row0]);
            float x01 = __ldcs(&LB[(size_t)(n0 + 1) * 1024 + row0]);
            float x10 = __ldcs(&LB[(size_t)(n0    ) * 1024 + row1]);
            float x11 = __ldcs(&LB[(size_t)(n0 + 1) * 1024 + row1]);
            float x20 = __ldcs(&LB[(size_t)(n0 + 8) * 1024 + row0]);
            float x21 = __ldcs(&LB[(size_t)(n0 + 9) * 1024 + row0]);
            float x30 = __ldcs(&LB[(size_t)(n0 + 8) * 1024 + row1]);
            float x31 = __ldcs(&LB[(size_t)(n0 + 9) * 1024 + row1]);
            split2(x00, x01, ah[k][0], al[k][0]);
            split2(x10, x11, ah[k][1], al[k][1]);
            split2(x20, x21, ah[k][2], al[k][2]);
            split2(x30, x31, ah[k][3], al[k][3]);
            xn0 += x00*x00 + x01*x01 + x20*x20 + x21*x21;
            xn1 += x10*x10 + x11*x11 + x30*x30 + x31*x31;
        }
        xn0 += __shfl_xor_sync(~0u, xn0, 1);
        xn0 += __shfl_xor_sync(~0u, xn0, 2);
        xn1 += __shfl_xor_sync(~0u, xn1, 1);
        xn1 += __shfl_xor_sync(~0u, xn1, 2);
    }

    float vmin0 = 3.4e38f, vmin1 = 3.4e38f;
    int   imin0 = 0,       imin1 = 0;
    const float2 zero2 = make_float2(0.f, 0.f);

    for (int ch = 0; ch < 8; ch++) {
        __syncthreads();   // prev chunk's mma + staging reads done
        // ---- stage prepacked B chunk: coalesced LDG.128 -> STS.128 ----
        {
            const uint4* GH = (const uint4*)(g_whi + ch * 4096);
            const uint4* GL = (const uint4*)(g_wlo + ch * 4096);
            #pragma unroll
            for (int q = 0; q < 4; q++) {
                const int idx = tid + q * 256;
                const int kp = idx >> 5, c4 = idx & 31;
                *(uint4*)&SBHI[kp * BSTRIDE + c4 * 4] = GH[idx];
                *(uint4*)&SBLO[kp * BSTRIDE + c4 * 4] = GL[idx];
            }
        }
        __syncthreads();

        // ---- coalesced streaming zero-fill of this chunk's enc slice ----
        {
            float2* eb = (float2*)(out + OFF_ENC) + (size_t)blk * 65536 + ch * 64;
            #pragma unroll
            for (int i = 0; i < 32; i++) {
                const int idx = i * 256 + tid;
                const int r = idx >> 6, c2 = idx & 63;
                __stcs(eb + (size_t)r * 512 + c2, zero2);
            }
        }

        // ---- two col-halves: mma 8 tiles -> stage d in smem -> coalesced STG
        #pragma unroll
        for (int hg = 0; hg < 2; hg++) {
            float acc[8][4];
            #pragma unroll
            for (int tt = 0; tt < 8; tt++) {
                acc[tt][0] = 0.f; acc[tt][1] = 0.f;
                acc[tt][2] = 0.f; acc[tt][3] = 0.f;
            }
            #pragma unroll
            for (int k = 0; k < 4; k++) {
                #pragma unroll
                for (int tt = 0; tt < 8; tt++) {
                    const int nb = (hg * 8 + tt) * 8 + g;
                    const int kp = k * 8 + tg;
                    uint32_t bh0 = SBHI[(kp    ) * BSTRIDE + nb];
                    uint32_t bh1 = SBHI[(kp + 4) * BSTRIDE + nb];
                    uint32_t bl0 = SBLO[(kp    ) * BSTRIDE + nb];
                    uint32_t bl1 = SBLO[(kp + 4) * BSTRIDE + nb];
                    mma16816(acc[tt], ah[k], bh0, bh1);   // hi*hi
                    mma16816(acc[tt], al[k], bh0, bh1);   // lo*hi
                    mma16816(acc[tt], ah[k], bl0, bl1);   // hi*lo
                }
            }
            #pragma unroll
            for (int tt = 0; tt < 8; tt++) {
                const int cl  = tt * 8 + 2 * tg;            // col within half
                const int col = ch * 128 + hg * 64 + cl;    // global col
                const float2 wn = *(const float2*)&s_wn[col];
                float d00 = fmaf(-2.f, acc[tt][0], xn0 + wn.x);
                float d01 = fmaf(-2.f, acc[tt][1], xn0 + wn.y);
                float d10 = fmaf(-2.f, acc[tt][2], xn1 + wn.x);
                float d11 = fmaf(-2.f, acc[tt][3], xn1 + wn.y);
                *(float2*)&s_d[row0 * 68 + cl] = make_float2(d00, d01);
                *(float2*)&s_d[row1 * 68 + cl] = make_float2(d10, d11);
                if (d00 < vmin0) { vmin0 = d00; imin0 = col; }
                if (d01 < vmin0) { vmin0 = d01; imin0 = col + 1; }
                if (d10 < vmin1) { vmin1 = d10; imin1 = col; }
                if (d11 < vmin1) { vmin1 = d11; imin1 = col + 1; }
            }
            __syncthreads();
            // coalesced float2 stores: warp = one row (256B), 16 iters
            {
                const int r8 = tid >> 5;   // 8 rows per iter
                float2* db = (float2*)(out + OFF_DIST) +
                             ((size_t)blk * 128) * 512 + ch * 64 + hg * 32;
                #pragma unroll
                for (int i = 0; i < 16; i++) {
                    const int r = i * 8 + r8;
                    __stcs(&db[(size_t)r * 512 + lane],
                           *(const float2*)&s_d[r * 68 + lane * 2]);
                }
            }
            __syncthreads();   // s_d reusable
        }
    }

    // ---- argmin across tg lanes (rows are warp-exclusive) ----
    #pragma unroll
    for (int off = 1; off <= 2; off <<= 1) {
        float ov0 = __shfl_xor_sync(~0u, vmin0, off);
        int   oi0 = __shfl_xor_sync(~0u, imin0, off);
        if (ov0 < vmin0 || (ov0 == vmin0 && oi0 < imin0)) { vmin0 = ov0; imin0 = oi0; }
        float ov1 = __shfl_xor_sync(~0u, vmin1, off);
        int   oi1 = __shfl_xor_sync(~0u, imin1, off);
        if (ov1 < vmin1 || (ov1 == vmin1 && oi1 < imin1)) { vmin1 = ov1; imin1 = oi1; }
    }
    if (tg == 0) {
        s_rmin[row0] = vmin0; s_ridx[row0] = imin0;
        s_rmin[row1] = vmin1; s_ridx[row1] = imin1;
    }
    __syncthreads();

    if (tid < 128) {
        const int ii = s_ridx[tid];
        atomicAdd(&g_counts[ii], 1);
        out[OFF_ENC + (size_t)(blk * 128 + tid) * 1024 + ii] = 1.f;
        float v = s_rmin[tid];
        #pragma unroll
        for (int off = 16; off > 0; off >>= 1)
            v += __shfl_down_sync(~0u, v, off);
        if ((tid & 31) == 0) s_loss[tid >> 5] = v;
    }
    __syncthreads();
    if (tid == 0)
        atomicAdd(&g_loss_sum, s_loss[0] + s_loss[1] + s_loss[2] + s_loss[3]);

    // ---- quantized gather: stride-129 smem stage, coalesced writes ----
    {
        float* wq = (float*)SBHI;
        const int code = tid >> 1, gh = tid & 1;
        const float4* wp = (const float4*)(W + (size_t)s_ridx[code] * 64) + gh * 8;
        #pragma unroll
        for (int q = 0; q < 8; q++) {
            float4 v = wp[q];
            const int kk = (gh * 8 + q) * 4;
            wq[(kk + 0) * 129 + code] = v.x;
            wq[(kk + 1) * 129 + code] = v.y;
            wq[(kk + 2) * 129 + code] = v.z;
            wq[(kk + 3) * 129 + code] = v.w;
        }
        __syncthreads();
        float* qb = out + OFF_Q + (size_t)b * 65536 + jb;
        #pragma unroll
        for (int i = 0; i < 32; i++) {
            const int idx = i * 256 + tid;
            const int n = idx >> 7, rr = idx & 127;
            __stcs(&qb[(size_t)n * 1024 + rr], wq[n * 129 + rr]);
        }
    }
}

// --- k_final: perplexity + loss ----------------------------------------------
__global__ void k_final(float* __restrict__ out) {
    __shared__ float red[1024];
    const int k = threadIdx.x;
    const float p = (float)g_counts[k] / 32768.0f;
    red[k] = -p * logf(p + 1e-10f);
    __syncthreads();
    for (int s = 512; s > 0; s >>= 1) {
        if (k < s) red[k] += red[k + s];
        __syncthreads();
    }
    if (k == 0) {
        out[OFF_PERP] = expf(red[0]);
        out[OFF_LOSS] = 0.25f * g_loss_sum / 2097152.0f;
    }
}

// -----------------------------------------------------------------------------
extern "C" void kernel_launch(void* const* d_in, const int* in_sizes, int n_in,
                              void* d_out, int out_size) {
    const float* latent = (const float*)d_in[0];
    const float* W      = (const float*)d_in[1];
    float* out = (float*)d_out;

    // opt-in >48KB dynamic smem; set only when needed (first, uncaptured call)
    cudaFuncAttributes fa;
    cudaFuncGetAttributes(&fa, k_main);
    if (fa.maxDynamicSharedSizeBytes < SMEM_BYTES)
        cudaFuncSetAttribute(k_main, cudaFuncAttributeMaxDynamicSharedMemorySize,
                             SMEM_BYTES);

    k_pre  <<<128, 256>>>(W);
    k_main <<<256, 256, SMEM_BYTES>>>(latent, W, out);
    k_final<<<1, 1024>>>(out);
}